// round 13
// baseline (speedup 1.0000x reference)
#include <cuda_runtime.h>
#include <cuda_fp16.h>
#include <cstdint>

#define DK 128
#define NB 4096
#define NC 16384
#define TM 128
#define TN 128
#define NTILES 4096            // 32 * 128

// smem layout (bytes): A strips resident, B 3-deep chunk ring
#define A0_OFF 0               // A strip parity 0: 128 x 256B (full K)
#define A1_OFF 32768           // A strip parity 1
#define B_OFF  65536           // 3 x 16KB B chunk buffers
#define BBUF   16384
#define SMEM_BYTES 114688      // 112 KB per CTA

// Scratch (allocation-free per harness rules)
__device__ __half g_xn[(size_t)NB * DK];
__device__ __half g_pn[(size_t)NC * DK];
__device__ float g_xs[NB];
__device__ float g_ps[NC];

__device__ __forceinline__ uint32_t smem_u32(const void* p) {
    return (uint32_t)__cvta_generic_to_shared(p);
}

// A: 256B rows (full K=128), u in 0..15 ; B: 128B rows (K chunk 64), u in 0..7
#define SWZA(row, u) ((uint32_t)((row) * 256 + (((u) ^ ((row) & 7)) << 4)))
#define SWZB(row, u) ((uint32_t)((row) * 128 + (((u) ^ ((row) & 7)) << 4)))

__device__ __forceinline__ void cp16(uint32_t dst, const __half* src) {
    asm volatile("cp.async.cg.shared.global [%0], [%1], 16;\n"
                 :: "r"(dst), "l"(__cvta_generic_to_global(src)) : "memory");
}

#define LDSM4(r0, r1, r2, r3, addr)                                          \
    asm volatile("ldmatrix.sync.aligned.m8n8.x4.shared.b16 {%0,%1,%2,%3}, [%4];" \
                 : "=r"(r0), "=r"(r1), "=r"(r2), "=r"(r3) : "r"(addr))

#define MMA16816(d, a, b0, b1)                                               \
    asm volatile("mma.sync.aligned.m16n8k16.row.col.f32.f16.f16.f32 "        \
                 "{%0,%1,%2,%3},{%4,%5,%6,%7},{%8,%9},{%0,%1,%2,%3};"        \
                 : "+f"(d[0]), "+f"(d[1]), "+f"(d[2]), "+f"(d[3])            \
                 : "r"(a[0]), "r"(a[1]), "r"(a[2]), "r"(a[3]), "r"(b0), "r"(b1))

// ---------------- fused normalize: one warp per row over both tensors ----------------
__global__ void normalize_all(const float* __restrict__ inputs,
                              const float* __restrict__ kern) {
    int wid = threadIdx.x >> 5;
    int lane = threadIdx.x & 31;
    int row = blockIdx.x * 8 + wid;
    const float* src;
    __half* dst;
    float* sums;
    int r;
    if (row < NB) { src = inputs; dst = g_xn; sums = g_xs; r = row; }
    else          { src = kern;   dst = g_pn; sums = g_ps; r = row - NB; }
    float4 x = *reinterpret_cast<const float4*>(src + (size_t)r * DK + lane * 4);
    float sq = x.x * x.x + x.y * x.y + x.z * x.z + x.w * x.w;
#pragma unroll
    for (int o = 16; o > 0; o >>= 1) sq += __shfl_xor_sync(0xffffffffu, sq, o);
    float m = fmaxf(sq, 1e-12f);
    float scale = 3.0f * rsqrtf(m);
    __half2 h0 = __floats2half2_rn(x.x * scale, x.y * scale);
    __half2 h1 = __floats2half2_rn(x.z * scale, x.w * scale);
    uint2 st;
    st.x = *reinterpret_cast<uint32_t*>(&h0);
    st.y = *reinterpret_cast<uint32_t*>(&h1);
    *reinterpret_cast<uint2*>(dst + (size_t)r * DK + lane * 4) = st;
    if (lane == 0) sums[r] = 9.0f * (sq / m);
}

// Load A strip (full K) for row-block bM_ into smem offset dstoff_
#define LOAD_A_STRIP(bM_, dstoff_)                                                \
    do {                                                                          \
        const __half* gA_ = g_xn + (size_t)(bM_)*TM * DK;                         \
        uint32_t ab_ = sbase + (uint32_t)(dstoff_);                               \
        _Pragma("unroll")                                                         \
        for (int j = tid; j < TM * 16; j += 128) {                                \
            int r_ = j >> 4, u_ = j & 15;                                         \
            cp16(ab_ + SWZA(r_, u_), gA_ + (size_t)r_ * DK + u_ * 8);             \
        }                                                                         \
    } while (0)

// Load B chunk (K64) of tile t_, chunk c_, into ring buffer b_
#define LOAD_B(t_, c_, b_)                                                        \
    do {                                                                          \
        int bN_ = (t_) >> 5;                                                      \
        const __half* gB_ = g_pn + (size_t)bN_ * TN * DK + (c_)*64;               \
        uint32_t bb_ = sbase + B_OFF + (uint32_t)(b_)*BBUF;                       \
        _Pragma("unroll")                                                         \
        for (int j = tid; j < TN * 8; j += 128) {                                 \
            int r_ = j >> 3, u_ = j & 7;                                          \
            cp16(bb_ + SWZB(r_, u_), gB_ + (size_t)r_ * DK + u_ * 8);             \
        }                                                                         \
        asm volatile("cp.async.commit_group;\n" ::: "memory");                    \
    } while (0)

#define COMPUTE_CHUNK(abase_, c_, bbase_)                                         \
    do {                                                                          \
        _Pragma("unroll")                                                         \
        for (int ks = 0; ks < 4; ks++) {                                          \
            uint32_t a[4][4], b[4][4];                                            \
            _Pragma("unroll")                                                     \
            for (int mi = 0; mi < 4; mi++)                                        \
                LDSM4(a[mi][0], a[mi][1], a[mi][2], a[mi][3],                     \
                      (abase_) + SWZA(a_row_base + mi * 16,                       \
                                      (c_)*8 + ks * 2 + a_u_add));                \
            _Pragma("unroll")                                                     \
            for (int nj = 0; nj < 4; nj++)                                        \
                LDSM4(b[nj][0], b[nj][1], b[nj][2], b[nj][3],                     \
                      (bbase_) + SWZB(b_row_base + nj * 16, ks * 2 + b_u_add));   \
            _Pragma("unroll")                                                     \
            for (int mi = 0; mi < 4; mi++)                                        \
                _Pragma("unroll")                                                 \
                for (int ni = 0; ni < 8; ni++)                                    \
                    MMA16816(acc[mi][ni], a[mi], b[ni >> 1][(ni & 1) * 2],        \
                             b[ni >> 1][(ni & 1) * 2 + 1]);                       \
        }                                                                         \
    } while (0)

__global__ void __launch_bounds__(128, 2) nca_gemm(float* __restrict__ out, int nCTA) {
    extern __shared__ char smem[];
    const int tid = threadIdx.x;
    const int wid = tid >> 5;
    const int lane = tid & 31;
    const int warpM = wid & 1;   // 0..1  (64 rows)
    const int warpN = wid >> 1;  // 0..1  (64 cols)
    const uint32_t sbase = smem_u32(smem);

    const int mseg = lane >> 3;
    const int mrow8 = lane & 7;
    const int a_row_base = warpM * 64 + ((mseg & 1) << 3) + mrow8;
    const int a_u_add = mseg >> 1;
    const int b_row_base = warpN * 64 + ((mseg >> 1) << 3) + mrow8;
    const int b_u_add = mseg & 1;
    const int lg = lane >> 2;
    const int tg = lane & 3;
    const int todd = tg & 1;

    const int t0 = blockIdx.x;
    const int ntiles = (NTILES - t0 + nCTA - 1) / nCTA;   // >= 1
    const int S = 2 * ntiles;

    // Prologue: both A strips (one group), then B chunks 0 and 1.
    // nCTA % 32 == 16 guarantees bM alternates between exactly two strips.
    LOAD_A_STRIP(t0 & 31, A0_OFF);
    LOAD_A_STRIP((t0 + nCTA) & 31, A1_OFF);
    asm volatile("cp.async.commit_group;\n" ::: "memory");
    LOAD_B(t0, 0, 0);
    LOAD_B(t0, 1, 1);

    float acc[4][8][4];

    for (int s = 0; s < S; s++) {
        const int ti = s >> 1;
        const int c = s & 1;
        const int t = t0 + ti * nCTA;

        if (s + 1 < S) {
            asm volatile("cp.async.wait_group 1;\n" ::: "memory");
        } else {
            asm volatile("cp.async.wait_group 0;\n" ::: "memory");
        }
        __syncthreads();

        // issue load for chunk s+2 (overwrites ring slot of chunk s-1; safe past sync)
        if (s + 2 < S) {
            const int s2 = s + 2;
            LOAD_B(t0 + (s2 >> 1) * nCTA, s2 & 1, s2 % 3);
        }

        if (c == 0) {
#pragma unroll
            for (int mi = 0; mi < 4; mi++)
#pragma unroll
                for (int ni = 0; ni < 8; ni++)
#pragma unroll
                    for (int r = 0; r < 4; r++) acc[mi][ni][r] = 0.0f;
        }

        const uint32_t abase = sbase + ((ti & 1) ? A1_OFF : A0_OFF);
        const uint32_t bbase = sbase + B_OFF + (uint32_t)(s % 3) * BBUF;
        COMPUTE_CHUNK(abase, c, bbase);

        if (c == 1) {
            // Epilogue: out = xs + ps - 2*dot, STG.128 via lane-pair exchange
            const int bM = t & 31, bN = t >> 5;
#pragma unroll
            for (int mi = 0; mi < 4; mi++) {
                int rbase = warpM * 64 + mi * 16 + lg;
                int r = rbase + (todd ? 8 : 0);
                float xs = __ldg(g_xs + bM * TM + r);
                size_t grow = (size_t)(bM * TM + r) * NC + bN * TN;
#pragma unroll
                for (int ni = 0; ni < 8; ni++) {
                    float v0 = acc[mi][ni][0], v1 = acc[mi][ni][1];
                    float v2 = acc[mi][ni][2], v3 = acc[mi][ni][3];
                    float s0 = __shfl_xor_sync(0xffffffffu, todd ? v0 : v2, 1);
                    float s1 = __shfl_xor_sync(0xffffffffu, todd ? v1 : v3, 1);
                    float w0 = todd ? s0 : v0;
                    float w1 = todd ? s1 : v1;
                    float w2 = todd ? v2 : s0;
                    float w3 = todd ? v3 : s1;
                    int cidx = warpN * 64 + ni * 8 + (tg & 2) * 2;
                    float4 pv = __ldg(reinterpret_cast<const float4*>(g_ps + bN * TN + cidx));
                    float4 o;
                    o.x = xs + pv.x - 2.0f * w0;
                    o.y = xs + pv.y - 2.0f * w1;
                    o.z = xs + pv.z - 2.0f * w2;
                    o.w = xs + pv.w - 2.0f * w3;
                    *reinterpret_cast<float4*>(out + grow + cidx) = o;
                }
            }
        }
    }
}

extern "C" void kernel_launch(void* const* d_in, const int* in_sizes, int n_in,
                              void* d_out, int out_size) {
    const float* inputs = (const float*)d_in[0];   // [4096, 128]
    const float* kern   = (const float*)d_in[1];   // [16384, 128]
    float* out = (float*)d_out;                    // [4096, 16384]

    normalize_all<<<(NB + NC) / 8, 256>>>(inputs, kern);

    int dev = 0, nsm = 152;
    cudaGetDevice(&dev);
    cudaDeviceGetAttribute(&nsm, cudaDevAttrMultiProcessorCount, dev);

    // force nCTA ≡ 16 (mod 32) so each CTA alternates between exactly 2 A strips
    int nCTA = 2 * nsm;
    nCTA = (nCTA & ~31) | 16;

    cudaFuncSetAttribute(nca_gemm, cudaFuncAttributeMaxDynamicSharedMemorySize, SMEM_BYTES);
    nca_gemm<<<nCTA, 128, SMEM_BYTES>>>(out, nCTA);
}

// round 14
// speedup vs baseline: 1.0262x; 1.0262x over previous
#include <cuda_runtime.h>
#include <cuda_fp16.h>
#include <cstdint>

#define DK 128
#define NB 4096
#define NC 16384
#define TM 128
#define TN 128
#define NTILES 4096            // 32 * 128

#define BUF_BYTES 32768        // A chunk 16KB + B chunk 16KB
#define SMEM_BYTES 65536       // 2 buffers

// Scratch (allocation-free per harness rules)
__device__ __half g_xn[(size_t)NB * DK];
__device__ __half g_pn[(size_t)NC * DK];
__device__ float g_xs[NB];
__device__ float g_ps[NC];

__device__ __forceinline__ uint32_t smem_u32(const void* p) {
    return (uint32_t)__cvta_generic_to_shared(p);
}

// 128B rows (K-chunk = 64 fp16), 8 x 16B chunks, XOR swizzle: conflict-free
__device__ __forceinline__ uint32_t swz(int row, int u) {
    return (uint32_t)(row * 128 + ((u ^ (row & 7)) << 4));
}

__device__ __forceinline__ void cp16(uint32_t dst, const __half* src) {
    asm volatile("cp.async.cg.shared.global [%0], [%1], 16;\n"
                 :: "r"(dst), "l"(__cvta_generic_to_global(src)) : "memory");
}

#define LDSM4(r0, r1, r2, r3, addr)                                          \
    asm volatile("ldmatrix.sync.aligned.m8n8.x4.shared.b16 {%0,%1,%2,%3}, [%4];" \
                 : "=r"(r0), "=r"(r1), "=r"(r2), "=r"(r3) : "r"(addr))

// f16 accumulator MMA: d/c are 2 x f16x2 registers
#define MMA16816H(d, a, b0, b1)                                              \
    asm volatile("mma.sync.aligned.m16n8k16.row.col.f16.f16.f16.f16 "        \
                 "{%0,%1},{%2,%3,%4,%5},{%6,%7},{%0,%1};"                    \
                 : "+r"(d[0]), "+r"(d[1])                                    \
                 : "r"(a[0]), "r"(a[1]), "r"(a[2]), "r"(a[3]), "r"(b0), "r"(b1))

// ---------------- fused normalize: one warp per row over both tensors ----------------
__global__ void normalize_all(const float* __restrict__ inputs,
                              const float* __restrict__ kern) {
    int wid = threadIdx.x >> 5;
    int lane = threadIdx.x & 31;
    int row = blockIdx.x * 8 + wid;
    const float* src;
    __half* dst;
    float* sums;
    int r;
    if (row < NB) { src = inputs; dst = g_xn; sums = g_xs; r = row; }
    else          { src = kern;   dst = g_pn; sums = g_ps; r = row - NB; }
    float4 x = *reinterpret_cast<const float4*>(src + (size_t)r * DK + lane * 4);
    float sq = x.x * x.x + x.y * x.y + x.z * x.z + x.w * x.w;
#pragma unroll
    for (int o = 16; o > 0; o >>= 1) sq += __shfl_xor_sync(0xffffffffu, sq, o);
    float m = fmaxf(sq, 1e-12f);
    float scale = 3.0f * rsqrtf(m);
    __half2 h0 = __floats2half2_rn(x.x * scale, x.y * scale);
    __half2 h1 = __floats2half2_rn(x.z * scale, x.w * scale);
    uint2 st;
    st.x = *reinterpret_cast<uint32_t*>(&h0);
    st.y = *reinterpret_cast<uint32_t*>(&h1);
    *reinterpret_cast<uint2*>(dst + (size_t)r * DK + lane * 4) = st;
    if (lane == 0) sums[r] = 9.0f * (sq / m);
}

// Load one 64-wide K chunk of tile t_ into buffer buf_ (A 128x64h + B 128x64h)
#define LOAD_CHUNK(t_, c_, buf_)                                                  \
    do {                                                                          \
        int bM_ = (t_) & 31, bN_ = (t_) >> 5;                                     \
        const __half* gA_ = g_xn + (size_t)bM_ * TM * DK + (c_)*64;               \
        const __half* gB_ = g_pn + (size_t)bN_ * TN * DK + (c_)*64;               \
        uint32_t ab_ = sbase + (uint32_t)(buf_)*BUF_BYTES;                        \
        uint32_t bb_ = ab_ + 16384;                                               \
        _Pragma("unroll")                                                         \
        for (int j = tid; j < TM * 8; j += 128) {                                 \
            int r_ = j >> 3, u_ = j & 7;                                          \
            cp16(ab_ + swz(r_, u_), gA_ + (size_t)r_ * DK + u_ * 8);              \
        }                                                                         \
        _Pragma("unroll")                                                         \
        for (int j = tid; j < TN * 8; j += 128) {                                 \
            int r_ = j >> 3, u_ = j & 7;                                          \
            cp16(bb_ + swz(r_, u_), gB_ + (size_t)r_ * DK + u_ * 8);              \
        }                                                                         \
        asm volatile("cp.async.commit_group;\n" ::: "memory");                    \
    } while (0)

#define COMPUTE_CHUNK(buf_)                                                       \
    do {                                                                          \
        const uint32_t aoff_ = sbase + (uint32_t)(buf_)*BUF_BYTES;                \
        const uint32_t boff_ = aoff_ + 16384;                                     \
        _Pragma("unroll")                                                         \
        for (int ks = 0; ks < 4; ks++) {                                          \
            const int ub = ks * 2;                                                \
            uint32_t a[4][4], b[4][4];                                            \
            _Pragma("unroll")                                                     \
            for (int mi = 0; mi < 4; mi++)                                        \
                LDSM4(a[mi][0], a[mi][1], a[mi][2], a[mi][3],                     \
                      aoff_ + swz(a_row_base + mi * 16, ub + a_u_add));           \
            _Pragma("unroll")                                                     \
            for (int nj = 0; nj < 4; nj++)                                        \
                LDSM4(b[nj][0], b[nj][1], b[nj][2], b[nj][3],                     \
                      boff_ + swz(b_row_base + nj * 16, ub + b_u_add));           \
            _Pragma("unroll")                                                     \
            for (int mi = 0; mi < 4; mi++)                                        \
                _Pragma("unroll")                                                 \
                for (int ni = 0; ni < 8; ni++)                                    \
                    MMA16816H(acc[mi][ni], a[mi], b[ni >> 1][(ni & 1) * 2],       \
                              b[ni >> 1][(ni & 1) * 2 + 1]);                      \
        }                                                                         \
    } while (0)

__global__ void __launch_bounds__(128, 3) nca_gemm(float* __restrict__ out, int nCTA) {
    extern __shared__ char smem[];
    const int tid = threadIdx.x;
    const int wid = tid >> 5;
    const int lane = tid & 31;
    const int warpM = wid & 1;   // 0..1  (64 rows)
    const int warpN = wid >> 1;  // 0..1  (64 cols)
    const uint32_t sbase = smem_u32(smem);

    const int mseg = lane >> 3;
    const int mrow8 = lane & 7;
    const int a_row_base = warpM * 64 + ((mseg & 1) << 3) + mrow8;
    const int a_u_add = mseg >> 1;
    const int b_row_base = warpN * 64 + ((mseg >> 1) << 3) + mrow8;
    const int b_u_add = mseg & 1;
    const int lg = lane >> 2;
    const int tg = lane & 3;
    const int todd = tg & 1;

    const int t0 = blockIdx.x;
    if (t0 < NTILES) {
        LOAD_CHUNK(t0, 0, 0);
        LOAD_CHUNK(t0, 1, 1);
    }

    for (int t = t0; t < NTILES; t += nCTA) {
        const int nt = t + nCTA;

        // f16x2 accumulators: [mi][ni] -> {rows lg / lg+8, cols 2tg,2tg+1}
        uint32_t acc[4][8][2];
#pragma unroll
        for (int mi = 0; mi < 4; mi++)
#pragma unroll
            for (int ni = 0; ni < 8; ni++) {
                acc[mi][ni][0] = 0u;
                acc[mi][ni][1] = 0u;
            }

        asm volatile("cp.async.wait_group 1;\n" ::: "memory");
        __syncthreads();
        COMPUTE_CHUNK(0);
        __syncthreads();
        if (nt < NTILES) LOAD_CHUNK(nt, 0, 0);

        if (nt < NTILES) {
            asm volatile("cp.async.wait_group 1;\n" ::: "memory");
        } else {
            asm volatile("cp.async.wait_group 0;\n" ::: "memory");
        }
        __syncthreads();
        COMPUTE_CHUNK(1);
        __syncthreads();
        if (nt < NTILES) LOAD_CHUNK(nt, 1, 1);

        // Epilogue: unpack f16x2 -> f32, out = xs + ps - 2*dot, STG.128 pairing
        const int bM = t & 31, bN = t >> 5;
#pragma unroll
        for (int mi = 0; mi < 4; mi++) {
            int rbase = warpM * 64 + mi * 16 + lg;
            int r = rbase + (todd ? 8 : 0);
            float xs = __ldg(g_xs + bM * TM + r);
            size_t grow = (size_t)(bM * TM + r) * NC + bN * TN;
#pragma unroll
            for (int ni = 0; ni < 8; ni++) {
                float2 d0 = __half22float2(*reinterpret_cast<__half2*>(&acc[mi][ni][0]));
                float2 d1 = __half22float2(*reinterpret_cast<__half2*>(&acc[mi][ni][1]));
                float v0 = d0.x, v1 = d0.y, v2 = d1.x, v3 = d1.y;
                float s0 = __shfl_xor_sync(0xffffffffu, todd ? v0 : v2, 1);
                float s1 = __shfl_xor_sync(0xffffffffu, todd ? v1 : v3, 1);
                float w0 = todd ? s0 : v0;
                float w1 = todd ? s1 : v1;
                float w2 = todd ? v2 : s0;
                float w3 = todd ? v3 : s1;
                int cidx = warpN * 64 + ni * 8 + (tg & 2) * 2;
                float4 pv = __ldg(reinterpret_cast<const float4*>(g_ps + bN * TN + cidx));
                float4 o;
                o.x = xs + pv.x - 2.0f * w0;
                o.y = xs + pv.y - 2.0f * w1;
                o.z = xs + pv.z - 2.0f * w2;
                o.w = xs + pv.w - 2.0f * w3;
                *reinterpret_cast<float4*>(out + grow + cidx) = o;
            }
        }
    }
}

extern "C" void kernel_launch(void* const* d_in, const int* in_sizes, int n_in,
                              void* d_out, int out_size) {
    const float* inputs = (const float*)d_in[0];   // [4096, 128]
    const float* kern   = (const float*)d_in[1];   // [16384, 128]
    float* out = (float*)d_out;                    // [4096, 16384]

    normalize_all<<<(NB + NC) / 8, 256>>>(inputs, kern);

    int dev = 0, nsm = 152;
    cudaGetDevice(&dev);
    cudaDeviceGetAttribute(&nsm, cudaDevAttrMultiProcessorCount, dev);

    cudaFuncSetAttribute(nca_gemm, cudaFuncAttributeMaxDynamicSharedMemorySize, SMEM_BYTES);
    int nCTA = 3 * nsm;
    nca_gemm<<<nCTA, 128, SMEM_BYTES>>>(out, nCTA);
}